// round 2
// baseline (speedup 1.0000x reference)
#include <cuda_runtime.h>

#define NBLK 1184
#define NTHR 256

// Per-block partial sums (deterministic reduction, no atomics on data).
__device__ float g_part_p[NBLK];   // sum of -(target*log p + (1-target)*log(1-p))
__device__ float g_part_ll[NBLK];  // sum of log-likelihood over paid elements
__device__ float g_part_np[NBLK];  // count of paid elements
__device__ unsigned g_ticket = 0;  // self-resetting last-block-done counter

__device__ __forceinline__ float frcp(float x) {
    float y;
    asm("rcp.approx.f32 %0, %1;" : "=f"(y) : "f"(x));
    return y;
}

struct Acc { float p, ll, np; };

// One scalar element: mirrors the reference formula exactly (including the
// unstable sigmoid-difference + max(.,EPS) clamp behavior in float32).
__device__ __forceinline__ void process_elem(
    float p, float t,
    float m0, float s0, float w0,
    float m1, float s1, float w1,
    float m2, float s2, float w2,
    Acc& a)
{
    const float EPS = 1e-8f;
    const float HB  = 0.05f;   // HALF_BIN

    float lik = 0.f;
    {
        float inv = frcp(s0 + EPS);
        float su  = frcp(1.f + __expf(-((t + HB - m0) * inv)));
        float sl  = frcp(1.f + __expf(-((t - HB - m0) * inv)));
        lik += w0 * fmaxf(su - sl, EPS);
    }
    {
        float inv = frcp(s1 + EPS);
        float su  = frcp(1.f + __expf(-((t + HB - m1) * inv)));
        float sl  = frcp(1.f + __expf(-((t - HB - m1) * inv)));
        lik += w1 * fmaxf(su - sl, EPS);
    }
    {
        float inv = frcp(s2 + EPS);
        float su  = frcp(1.f + __expf(-((t + HB - m2) * inv)));
        float sl  = frcp(1.f + __expf(-((t - HB - m2) * inv)));
        lik += w2 * fmaxf(su - sl, EPS);
    }

    bool paid = (t > 0.f);
    float ll = __logf(lik + EPS);
    if (paid) { a.ll += ll; a.np += 1.f; }

    // target*log(p) + (1-target)*log(1-p) == log(paid ? p : 1-p); clip >= -100
    float q = paid ? p : (1.f - p);
    a.p -= fmaxf(__logf(q), -100.f);
}

__global__ void __launch_bounds__(NTHR) zimol_fused(
    const float* __restrict__ pp, const float* __restrict__ mu,
    const float* __restrict__ sg, const float* __restrict__ wt,
    const float* __restrict__ tv, float* __restrict__ out, int B)
{
    const int nvec = B >> 2;            // float4 vectors per row
    Acc a = {0.f, 0.f, 0.f};

    const float4* pp4 = reinterpret_cast<const float4*>(pp);
    const float4* tv4 = reinterpret_cast<const float4*>(tv);
    const float4* mu4 = reinterpret_cast<const float4*>(mu);
    const float4* sg4 = reinterpret_cast<const float4*>(sg);
    const float4* wt4 = reinterpret_cast<const float4*>(wt);

    for (int v = blockIdx.x * NTHR + threadIdx.x; v < nvec; v += NBLK * NTHR) {
        float4 p4 = __ldg(pp4 + v);
        float4 t4 = __ldg(tv4 + v);
        float4 m[3], s[3], w[3];
        #pragma unroll
        for (int k = 0; k < 3; k++) {
            m[k] = __ldg(mu4 + k * nvec + v);
            s[k] = __ldg(sg4 + k * nvec + v);
            w[k] = __ldg(wt4 + k * nvec + v);
        }
        process_elem(p4.x, t4.x, m[0].x, s[0].x, w[0].x,
                     m[1].x, s[1].x, w[1].x, m[2].x, s[2].x, w[2].x, a);
        process_elem(p4.y, t4.y, m[0].y, s[0].y, w[0].y,
                     m[1].y, s[1].y, w[1].y, m[2].y, s[2].y, w[2].y, a);
        process_elem(p4.z, t4.z, m[0].z, s[0].z, w[0].z,
                     m[1].z, s[1].z, w[1].z, m[2].z, s[2].z, w[2].z, a);
        process_elem(p4.w, t4.w, m[0].w, s[0].w, w[0].w,
                     m[1].w, s[1].w, w[1].w, m[2].w, s[2].w, w[2].w, a);
    }

    // Scalar tail (B not divisible by 4) — robustness; no-op for B = 4M.
    int tail = B & 3;
    if (tail) {
        int base = nvec << 2;
        int i = blockIdx.x * NTHR + threadIdx.x;
        if (i < tail) {
            int idx = base + i;
            process_elem(pp[idx], tv[idx],
                         mu[0 * B + idx], sg[0 * B + idx], wt[0 * B + idx],
                         mu[1 * B + idx], sg[1 * B + idx], wt[1 * B + idx],
                         mu[2 * B + idx], sg[2 * B + idx], wt[2 * B + idx], a);
        }
    }

    // ---- Block reduction ----
    #pragma unroll
    for (int o = 16; o > 0; o >>= 1) {
        a.p  += __shfl_down_sync(0xffffffffu, a.p,  o);
        a.ll += __shfl_down_sync(0xffffffffu, a.ll, o);
        a.np += __shfl_down_sync(0xffffffffu, a.np, o);
    }

    __shared__ float shp[8], shl[8], shn[8];
    __shared__ bool s_last;
    int wid  = threadIdx.x >> 5;
    int lane = threadIdx.x & 31;
    if (lane == 0) { shp[wid] = a.p; shl[wid] = a.ll; shn[wid] = a.np; }
    __syncthreads();

    if (threadIdx.x == 0) {
        float vp = 0.f, vl = 0.f, vn = 0.f;
        #pragma unroll
        for (int i = 0; i < 8; i++) { vp += shp[i]; vl += shl[i]; vn += shn[i]; }
        g_part_p[blockIdx.x]  = vp;
        g_part_ll[blockIdx.x] = vl;
        g_part_np[blockIdx.x] = vn;
        // Make partials globally visible before taking a ticket.
        __threadfence();
        unsigned t = atomicAdd(&g_ticket, 1u);
        s_last = (t == (unsigned)(NBLK - 1));
        if (s_last) g_ticket = 0u;   // self-reset: deterministic across replays
    }
    __syncthreads();

    // ---- Last block finalizes ----
    if (s_last) {
        double sp = 0.0, sl = 0.0, sn = 0.0;
        for (int i = threadIdx.x; i < NBLK; i += NTHR) {
            sp += (double)g_part_p[i];
            sl += (double)g_part_ll[i];
            sn += (double)g_part_np[i];
        }
        __shared__ double dp[NTHR], dl[NTHR], dn[NTHR];
        dp[threadIdx.x] = sp; dl[threadIdx.x] = sl; dn[threadIdx.x] = sn;
        __syncthreads();
        for (int s = NTHR / 2; s > 0; s >>= 1) {
            if (threadIdx.x < s) {
                dp[threadIdx.x] += dp[threadIdx.x + s];
                dl[threadIdx.x] += dl[threadIdx.x + s];
                dn[threadIdx.x] += dn[threadIdx.x + s];
            }
            __syncthreads();
        }
        if (threadIdx.x == 0) {
            float purchase = (float)dp[0] / (float)B;
            float n   = (float)dn[0];
            float ltv = (n > 0.f) ? -((float)dl[0] / fmaxf(n, 1.f)) : 0.f;
            out[0] = purchase + ltv;
        }
    }
}

extern "C" void kernel_launch(void* const* d_in, const int* in_sizes, int n_in,
                              void* d_out, int out_size)
{
    const float* pp = (const float*)d_in[0];  // predicted_purchase_prob (B,)
    const float* mu = (const float*)d_in[1];  // mu     (K,B)
    const float* sg = (const float*)d_in[2];  // sigma  (K,B)
    const float* wt = (const float*)d_in[3];  // weight (K,B)
    const float* tv = (const float*)d_in[4];  // true_values (B,)
    int B = in_sizes[0];

    zimol_fused<<<NBLK, NTHR>>>(pp, mu, sg, wt, tv, (float*)d_out, B);
}

// round 3
// speedup vs baseline: 1.1533x; 1.1533x over previous
#include <cuda_runtime.h>

#define NBLK 740            // 148 SMs x 5 resident CTAs: exactly one wave
#define NTHR 256

// Per-block partial sums (deterministic reduction, no data atomics).
__device__ float g_part_p[NBLK];
__device__ float g_part_ll[NBLK];
__device__ float g_part_np[NBLK];
__device__ unsigned g_ticket = 0;   // self-resetting last-block-done counter

__device__ __forceinline__ float frcp(float x) {
    float y;
    asm("rcp.approx.f32 %0, %1;" : "=f"(y) : "f"(x));
    return y;
}

struct Acc { float p, ll, np; };

// One scalar element: mirrors the reference formula exactly (including the
// unstable sigmoid-difference + max(.,EPS) clamp behavior in float32).
__device__ __forceinline__ void process_elem(
    float p, float t,
    float m0, float s0, float w0,
    float m1, float s1, float w1,
    float m2, float s2, float w2,
    Acc& a)
{
    const float EPS = 1e-8f;
    const float HB  = 0.05f;   // HALF_BIN

    float lik = 0.f;
    {
        float inv = frcp(s0 + EPS);
        float su  = frcp(1.f + __expf(-((t + HB - m0) * inv)));
        float sl  = frcp(1.f + __expf(-((t - HB - m0) * inv)));
        lik += w0 * fmaxf(su - sl, EPS);
    }
    {
        float inv = frcp(s1 + EPS);
        float su  = frcp(1.f + __expf(-((t + HB - m1) * inv)));
        float sl  = frcp(1.f + __expf(-((t - HB - m1) * inv)));
        lik += w1 * fmaxf(su - sl, EPS);
    }
    {
        float inv = frcp(s2 + EPS);
        float su  = frcp(1.f + __expf(-((t + HB - m2) * inv)));
        float sl  = frcp(1.f + __expf(-((t - HB - m2) * inv)));
        lik += w2 * fmaxf(su - sl, EPS);
    }

    bool paid = (t > 0.f);
    float ll = __logf(lik + EPS);
    if (paid) { a.ll += ll; a.np += 1.f; }

    float q = paid ? p : (1.f - p);
    a.p -= fmaxf(__logf(q), -100.f);
}

__global__ void __launch_bounds__(NTHR, 5) zimol_fused(
    const float* __restrict__ pp, const float* __restrict__ mu,
    const float* __restrict__ sg, const float* __restrict__ wt,
    const float* __restrict__ tv, float* __restrict__ out, int B)
{
    const int nvec = B >> 2;            // float4 vectors per row
    Acc a = {0.f, 0.f, 0.f};

    const float4* pp4 = reinterpret_cast<const float4*>(pp);
    const float4* tv4 = reinterpret_cast<const float4*>(tv);
    const float4* mu4 = reinterpret_cast<const float4*>(mu);
    const float4* sg4 = reinterpret_cast<const float4*>(sg);
    const float4* wt4 = reinterpret_cast<const float4*>(wt);

    for (int v = blockIdx.x * NTHR + threadIdx.x; v < nvec; v += NBLK * NTHR) {
        float4 p4 = __ldg(pp4 + v);
        float4 t4 = __ldg(tv4 + v);
        float4 m[3], s[3], w[3];
        #pragma unroll
        for (int k = 0; k < 3; k++) {
            m[k] = __ldg(mu4 + k * nvec + v);
            s[k] = __ldg(sg4 + k * nvec + v);
            w[k] = __ldg(wt4 + k * nvec + v);
        }
        process_elem(p4.x, t4.x, m[0].x, s[0].x, w[0].x,
                     m[1].x, s[1].x, w[1].x, m[2].x, s[2].x, w[2].x, a);
        process_elem(p4.y, t4.y, m[0].y, s[0].y, w[0].y,
                     m[1].y, s[1].y, w[1].y, m[2].y, s[2].y, w[2].y, a);
        process_elem(p4.z, t4.z, m[0].z, s[0].z, w[0].z,
                     m[1].z, s[1].z, w[1].z, m[2].z, s[2].z, w[2].z, a);
        process_elem(p4.w, t4.w, m[0].w, s[0].w, w[0].w,
                     m[1].w, s[1].w, w[1].w, m[2].w, s[2].w, w[2].w, a);
    }

    // Scalar tail (B not divisible by 4) — robustness; no-op for B = 4M.
    int tail = B & 3;
    if (tail) {
        int base = nvec << 2;
        int i = blockIdx.x * NTHR + threadIdx.x;
        if (i < tail) {
            int idx = base + i;
            process_elem(pp[idx], tv[idx],
                         mu[0 * B + idx], sg[0 * B + idx], wt[0 * B + idx],
                         mu[1 * B + idx], sg[1 * B + idx], wt[1 * B + idx],
                         mu[2 * B + idx], sg[2 * B + idx], wt[2 * B + idx], a);
        }
    }

    // ---- Block reduction (all float, shuffle + tiny smem) ----
    #pragma unroll
    for (int o = 16; o > 0; o >>= 1) {
        a.p  += __shfl_down_sync(0xffffffffu, a.p,  o);
        a.ll += __shfl_down_sync(0xffffffffu, a.ll, o);
        a.np += __shfl_down_sync(0xffffffffu, a.np, o);
    }

    __shared__ float shp[8], shl[8], shn[8];
    __shared__ bool s_last;
    int wid  = threadIdx.x >> 5;
    int lane = threadIdx.x & 31;
    if (lane == 0) { shp[wid] = a.p; shl[wid] = a.ll; shn[wid] = a.np; }
    __syncthreads();

    if (threadIdx.x == 0) {
        float vp = 0.f, vl = 0.f, vn = 0.f;
        #pragma unroll
        for (int i = 0; i < 8; i++) { vp += shp[i]; vl += shl[i]; vn += shn[i]; }
        g_part_p[blockIdx.x]  = vp;
        g_part_ll[blockIdx.x] = vl;
        g_part_np[blockIdx.x] = vn;
        __threadfence();
        unsigned t = atomicAdd(&g_ticket, 1u);
        s_last = (t == (unsigned)(NBLK - 1));
        if (s_last) g_ticket = 0u;   // self-reset: deterministic across replays
    }
    __syncthreads();

    // ---- Last block finalizes (float, 740 partials) ----
    if (s_last) {
        float sp = 0.f, sl = 0.f, sn = 0.f;
        for (int i = threadIdx.x; i < NBLK; i += NTHR) {
            sp += g_part_p[i];
            sl += g_part_ll[i];
            sn += g_part_np[i];
        }
        #pragma unroll
        for (int o = 16; o > 0; o >>= 1) {
            sp += __shfl_down_sync(0xffffffffu, sp, o);
            sl += __shfl_down_sync(0xffffffffu, sl, o);
            sn += __shfl_down_sync(0xffffffffu, sn, o);
        }
        if (lane == 0) { shp[wid] = sp; shl[wid] = sl; shn[wid] = sn; }
        __syncthreads();
        if (threadIdx.x == 0) {
            float vp = 0.f, vl = 0.f, vn = 0.f;
            #pragma unroll
            for (int i = 0; i < 8; i++) { vp += shp[i]; vl += shl[i]; vn += shn[i]; }
            float purchase = vp / (float)B;
            float ltv = (vn > 0.f) ? -(vl / fmaxf(vn, 1.f)) : 0.f;
            out[0] = purchase + ltv;
        }
    }
}

extern "C" void kernel_launch(void* const* d_in, const int* in_sizes, int n_in,
                              void* d_out, int out_size)
{
    const float* pp = (const float*)d_in[0];  // predicted_purchase_prob (B,)
    const float* mu = (const float*)d_in[1];  // mu     (K,B)
    const float* sg = (const float*)d_in[2];  // sigma  (K,B)
    const float* wt = (const float*)d_in[3];  // weight (K,B)
    const float* tv = (const float*)d_in[4];  // true_values (B,)
    int B = in_sizes[0];

    zimol_fused<<<NBLK, NTHR>>>(pp, mu, sg, wt, tv, (float*)d_out, B);
}